// round 13
// baseline (speedup 1.0000x reference)
#include <cuda_runtime.h>
#include <cstdint>

// PixelShuffle / depth-to-space, R=2, feature-major channel grouping.
//   out[b, 2x+i, 2y+j, f] = in[b, x, y, 4f + 2i + j]
// in : [B=8, X=256, Y=256, C=256] fp32   (512 MiB)
// out: [B=8, 512, 512, 64]        fp32   (512 MiB)
//
// FINAL. Pure streaming permutation at the mixed read+write HBM ceiling.
// Seven clean measurements: kernel 149.3-150.8us, 6.8 TB/s = 85-86% of
// 8 TB/s spec; measured traffic = exactly the mandatory 1 GiB (no wasted
// bytes). DRAM is the only saturated resource (L2 42%, L1 50%, issue 6%);
// occupancy proven non-binding (57% vs 81% identical perf). History:
//   v1 16t/pixel float4 transpose    149.6us  baseline winner
//   v2 8t/pixel, 8-wide ILP          182us    REGRESSED (regs 46, occ 52%)
//   v3 v1 + __ldcs/__stcs            150.3us  neutral
//   v5 v3 + u32 indexing             149.3-150.8us plateau (5 samples)
// Ruled out by measurement or HW model: TMA/SMEM staging (LTS cap is
// path-independent; MC scheduling invisible to kernel), multicast (zero
// shared reads), larger stores (STG.128 is ISA max), occupancy tuning.
// Residual vs spec is HBM bus turnaround - not kernel-controllable.
//
// Layout: 16 threads per input pixel; thread t loads 4 consecutive float4s
// (features 4t..4t+3), register-transposes, stores one float4 per output
// quadrant. Half-warp loads: contiguous 512 B run; each quadrant store per
// half-warp: contiguous 256 B run; all sectors full.

static constexpr int C_ = 256;              // 64 features * 4
static constexpr int F4_PER_PIX_OUT = 16;   // 64 feat / 4
static constexpr unsigned N_THREADS = 8u * 256u * 256u * 16u;  // B*X*Y*16

__global__ __launch_bounds__(256)
void pixelshuffle_kernel(const float4* __restrict__ in, float4* __restrict__ out) {
    unsigned g = blockIdx.x * blockDim.x + threadIdx.x;
    unsigned t     = g & 15u;    // 0..15: feature-quad index
    unsigned pixel = g >> 4;     // input pixel id, < B*X*Y = 2^19

    unsigned y  = pixel & 255u;          // Y_-1
    unsigned bx = pixel >> 8;            // b*256 + x  (b*X + x)

    // Input: pixel row is 64 float4s; thread t reads 4 consecutive float4s.
    const float4* src = in + pixel * (C_ / 4) + t * 4u;
    float4 v0 = __ldcs(src + 0);   // feature 4t+0, quadrants in .x/.y/.z/.w
    float4 v1 = __ldcs(src + 1);   // feature 4t+1
    float4 v2 = __ldcs(src + 2);   // feature 4t+2
    float4 v3 = __ldcs(src + 3);   // feature 4t+3

    // Output float4 index: ((b*512 + 2x+i)*512 + 2y+j)*16 + t
    //  = (2*bx + i)*8192 + (2y + j)*16 + t      (all fits in u32: max ~2^27)
    unsigned ob = (2u * bx) * 8192u + (2u * y) * 16u + t;
    const unsigned ROW = 8192u;  // one output row of float4s (512*16)

    // quadrant component index = 2i + j
    __stcs(out + ob,            make_float4(v0.x, v1.x, v2.x, v3.x)); // i=0, j=0
    __stcs(out + ob + 16,       make_float4(v0.y, v1.y, v2.y, v3.y)); // i=0, j=1
    __stcs(out + ob + ROW,      make_float4(v0.z, v1.z, v2.z, v3.z)); // i=1, j=0
    __stcs(out + ob + ROW + 16, make_float4(v0.w, v1.w, v2.w, v3.w)); // i=1, j=1
}

extern "C" void kernel_launch(void* const* d_in, const int* in_sizes, int n_in,
                              void* d_out, int out_size) {
    const float4* in = (const float4*)d_in[0];
    float4* out = (float4*)d_out;
    pixelshuffle_kernel<<<N_THREADS / 256u, 256u>>>(in, out);
}